// round 10
// baseline (speedup 1.0000x reference)
#include <cuda_runtime.h>

#define Bsz 4
#define Nn 300
#define TOP 36
#define Cc 2048
#define Dd 2048
#define NROI (Bsz*TOP)

// plane geometry
#define HS0 100
#define HS1 50
#define HS2 25
#define HS3 13
#define HW0 (HS0*HS0)   // 10000
#define HW1 (HS1*HS1)   // 2500
#define HW2 (HS2*HS2)   // 625
#define HW3 (HS3*HS3)   // 169
#define PB0 0
#define PB1 HW0
#define PB2 (HW0+HW1)
#define PB3 (HW0+HW1+HW2)
#define PTOT (HW0+HW1+HW2+HW3)    // 13294 floats

// dynamic smem layout for pool (floats)
#define OFF_SYI  PTOT                 // 13294 (int view)   36*28
#define OFF_SYW  (OFF_SYI + TOP*28)   // 14302
#define OFF_SXI  (OFF_SYW + TOP*28)   // 15310 (int view)
#define OFF_SXW  (OFF_SXI + TOP*28)   // 16318
#define OFF_META (OFF_SXW + TOP*28)   // 17326 (int view)   36*3
#define POOL_SMEM_FLOATS (OFF_META + TOP*3)
#define POOL_SMEM_BYTES  (POOL_SMEM_FLOATS * 4)

// ---------------- scratch (device globals, no allocation) ----------------
__device__ int   g_valid[NROI];
__device__ int   g_level[NROI];
__device__ int   g_dest[NROI];
__device__ int   g_ny[NROI], g_nx[NROI];
__device__ int   g_yi[NROI][28], g_xi[NROI][28];
__device__ float g_yw[NROI][28], g_xw[NROI][28];
__device__ float g_pooled[NROI][Cc];

#define KSPLIT 16
__device__ float g_part[KSPLIT][NROI][Dd];

__device__ __forceinline__ int level_size(int l) {
    return (l == 0) ? HS0 : (l == 1) ? HS1 : (l == 2) ? HS2 : HS3;
}

// Streaming separable axis table: 14 monotone samples -> merged (idx, weight)
// list (<=28 entries). Exactly replicates reference bilinear accumulation.
__device__ int build_axis(float start, float rlen, int Hs, int* gidx, float* gwt) {
    int   li[28];
    float lw[28];
    int n = 0;
    float step7  = rlen / 7.0f;
    float step14 = rlen / 14.0f;
    for (int i = 0; i < 14; i++) {
        float yy = start + (float)(i >> 1) * step7 + ((float)(i & 1) + 0.5f) * step14;
        if (yy < -1.0f || yy > (float)Hs) continue;
        float yc = fminf(fmaxf(yy, 0.0f), (float)Hs - 1.0f);
        int i0 = (int)floorf(yc);
        int i1 = min(i0 + 1, Hs - 1);
        float w = yc - (float)i0;
        float w0 = 1.0f - w;
        if (n > 0 && li[n-1] == i0)      lw[n-1] += w0;
        else if (n > 1 && li[n-2] == i0) lw[n-2] += w0;
        else { li[n] = i0; lw[n] = w0; n++; }
        if (n > 0 && li[n-1] == i1)      lw[n-1] += w;
        else if (n > 1 && li[n-2] == i1) lw[n-2] += w;
        else { li[n] = i1; lw[n] = w; n++; }
    }
    for (int t = 0; t < n; t++) { gidx[t] = li[t]; gwt[t] = lw[t]; }
    return n;
}

// ---------------- kernel 1: filter + sort + warp NMS + tables + dest ----------------
__global__ void select_kernel(const float* __restrict__ boxes,
                              const float* __restrict__ scores) {
    int b = blockIdx.x;
    int tid = threadIdx.x;
    __shared__ float ss[Nn];
    __shared__ float sx1[Nn], sy1[Nn], sx2[Nn], sy2[Nn];
    __shared__ int   s_selidx[TOP];
    __shared__ int   s_cnt;
    __shared__ int   s_M;
    __shared__ int   keys[TOP];

    const float* sc = scores + b * Nn;
    const float* bx = boxes + (size_t)b * Nn * 4;

    if (tid == 0) s_M = 0;
    for (int i = tid; i < Nn; i += blockDim.x) ss[i] = sc[i];
    __syncthreads();

    {
        int local = 0;
        for (int i = tid; i < Nn; i += blockDim.x) local += (ss[i] > 0.3f);
        #pragma unroll
        for (int o = 16; o; o >>= 1) local += __shfl_down_sync(0xffffffffu, local, o);
        if ((tid & 31) == 0 && local) atomicAdd(&s_M, local);
    }

    for (int i = tid; i < Nn; i += blockDim.x) {
        float si = ss[i];
        if (si > 0.3f) {
            int rank = 0;
            for (int j = 0; j < Nn; j++) {
                float sj = ss[j];
                rank += (sj > 0.3f) && ((sj > si) || (sj == si && j < i));
            }
            sx1[rank] = bx[i * 4 + 0];
            sy1[rank] = bx[i * 4 + 1];
            sx2[rank] = bx[i * 4 + 2];
            sy2[rank] = bx[i * 4 + 3];
        }
    }
    __syncthreads();

    int M = s_M;

    if (tid < 32) {
        int lane = tid;
        unsigned kmask = 0;
        #pragma unroll
        for (int s2 = 0; s2 < 10; s2++)
            if (lane + 32 * s2 < M) kmask |= (1u << s2);
        int cnt = 0;
        for (int i = 0; i < M; i++) {
            unsigned om = __shfl_sync(0xffffffffu, kmask, i & 31);
            if (!((om >> (i >> 5)) & 1u)) continue;
            if (lane == 0) s_selidx[cnt] = i;
            cnt++;
            if (cnt >= TOP) break;
            float x1 = sx1[i], y1 = sy1[i], x2 = sx2[i], y2 = sy2[i];
            float ai = (x2 - x1) * (y2 - y1);
            #pragma unroll
            for (int s2 = 0; s2 < 10; s2++) {
                int j = lane + 32 * s2;
                if (((kmask >> s2) & 1u) && j > i && j < M) {
                    float jx1 = sx1[j], jy1 = sy1[j], jx2 = sx2[j], jy2 = sy2[j];
                    float xx1 = fmaxf(x1, jx1);
                    float yy1 = fmaxf(y1, jy1);
                    float xx2 = fminf(x2, jx2);
                    float yy2 = fminf(y2, jy2);
                    float inter = fmaxf(xx2 - xx1, 0.0f) * fmaxf(yy2 - yy1, 0.0f);
                    float aj = (jx2 - jx1) * (jy2 - jy1);
                    float iou = inter / (ai + aj - inter);
                    if (iou > 0.7f) kmask &= ~(1u << s2);
                }
            }
        }
        if (lane == 0) s_cnt = cnt;
    }
    __syncthreads();

    if (tid < TOP) {
        int r = tid;
        int roi = b * TOP + r;
        int valid = 0, lvl = 0;
        if (r < s_cnt) {
            valid = 1;
            int i = s_selidx[r];
            float bx0 = sx1[i], bx1 = sy1[i], bx2 = sx2[i], bx3 = sy2[i];
            float dx = bx2 - bx0, dy = bx3 - bx1;
            float diag = sqrtf(dx * dx + dy * dy);
            float lf = floorf(4.0f + log2f(diag / 224.0f * 4.0f));
            lf = fminf(fmaxf(lf, 2.0f), 5.0f);
            lvl = (int)lf - 2;
            int Hs = level_size(lvl);
            float rw = fmaxf(bx2 - bx0, 1.0f);
            float rh = fmaxf(bx3 - bx1, 1.0f);
            g_ny[roi] = build_axis(bx1, rh, Hs, g_yi[roi], g_yw[roi]);
            g_nx[roi] = build_axis(bx0, rw, Hs, g_xi[roi], g_xw[roi]);
        } else {
            g_ny[roi] = 0;
            g_nx[roi] = 0;
        }
        g_valid[roi] = valid;
        g_level[roi] = lvl;
        keys[r] = valid ? (lvl * TOP + r) : (4 * TOP + r);
    }
    __syncthreads();
    if (tid < TOP) {
        int k = keys[tid];
        int d = 0;
        for (int q = 0; q < TOP; q++) d += (keys[q] < k);
        g_dest[b * TOP + tid] = d;
    }
}

// ---------------- kernel 2: plane-streaming ROI pooling ----------------
// Block = (channel, image). Streams all 4 planes of this channel into smem
// (contiguous float4 loads), then computes all 36 rois' separable pooled
// values from smem. 8192 identical-cost blocks -> perfect balance.
__global__ void __launch_bounds__(128) pool_kernel(
        const float* __restrict__ f0, const float* __restrict__ f1,
        const float* __restrict__ f2, const float* __restrict__ f3) {
    extern __shared__ float sm[];
    float* splane = sm;
    int*   syi  = (int*)(sm + OFF_SYI);
    float* syw  = sm + OFF_SYW;
    int*   sxi  = (int*)(sm + OFF_SXI);
    float* sxw  = sm + OFF_SXW;
    int*   smeta = (int*)(sm + OFF_META);

    int c   = blockIdx.x;
    int img = blockIdx.y;
    int tid = threadIdx.x;

    // roi tables for this image
    for (int i = tid; i < TOP * 28; i += 128) {
        int r = i / 28, j = i - (i / 28) * 28;
        int roi = img * TOP + r;
        syi[i] = g_yi[roi][j];
        syw[i] = g_yw[roi][j];
        sxi[i] = g_xi[roi][j];
        sxw[i] = g_xw[roi][j];
    }
    if (tid < TOP) {
        int roi = img * TOP + tid;
        smeta[tid * 3 + 0] = g_valid[roi] ? g_ny[roi] : 0;
        smeta[tid * 3 + 1] = g_nx[roi];
        smeta[tid * 3 + 2] = g_level[roi];
    }

    // stream planes (channel c of image img)
    {
        const float4* s0 = (const float4*)(f0 + (size_t)(img * Cc + c) * HW0);
        float4* d0 = (float4*)(splane + PB0);
        #pragma unroll 4
        for (int i = tid; i < HW0 / 4; i += 128) d0[i] = s0[i];
        const float4* s1 = (const float4*)(f1 + (size_t)(img * Cc + c) * HW1);
        float4* d1 = (float4*)(splane + PB1);
        #pragma unroll 2
        for (int i = tid; i < HW1 / 4; i += 128) d1[i] = s1[i];
        const float* s2 = f2 + (size_t)(img * Cc + c) * HW2;
        for (int i = tid; i < HW2; i += 128) splane[PB2 + i] = s2[i];
        const float* s3 = f3 + (size_t)(img * Cc + c) * HW3;
        for (int i = tid; i < HW3; i += 128) splane[PB3 + i] = s3[i];
    }
    __syncthreads();

    int warp = tid >> 5, lane = tid & 31;
    for (int r = warp; r < TOP; r += 4) {
        int ny  = smeta[r * 3 + 0];
        int roi = img * TOP + r;
        if (ny == 0) {
            if (lane == 0) g_pooled[roi][c] = 0.0f;
            continue;
        }
        int nx  = smeta[r * 3 + 1];
        int lvl = smeta[r * 3 + 2];
        int Hs  = level_size(lvl);
        int pb  = (lvl == 0) ? PB0 : (lvl == 1) ? PB1 : (lvl == 2) ? PB2 : PB3;

        float wxr = 0.0f;
        int   xo  = 0;
        if (lane < nx) { wxr = sxw[r * 28 + lane]; xo = sxi[r * 28 + lane]; }
        int   myi = (lane < ny) ? syi[r * 28 + lane] * Hs : 0;
        float myw = (lane < ny) ? syw[r * 28 + lane] : 0.0f;

        const float* base = splane + pb + xo;
        float acc0 = 0.0f, acc1 = 0.0f;
        int a = 0;
        for (; a + 1 < ny; a += 2) {
            int   y0 = __shfl_sync(0xffffffffu, myi, a);
            int   y1 = __shfl_sync(0xffffffffu, myi, a + 1);
            float w0 = __shfl_sync(0xffffffffu, myw, a);
            float w1 = __shfl_sync(0xffffffffu, myw, a + 1);
            acc0 += base[y0] * wxr * w0;
            acc1 += base[y1] * wxr * w1;
        }
        if (a < ny) {
            int   y0 = __shfl_sync(0xffffffffu, myi, a);
            float w0 = __shfl_sync(0xffffffffu, myw, a);
            acc0 += base[y0] * wxr * w0;
        }
        float acc = acc0 + acc1;
        #pragma unroll
        for (int o = 16; o; o >>= 1)
            acc += __shfl_down_sync(0xffffffffu, acc, o);
        if (lane == 0)
            g_pooled[roi][c] = acc * (1.0f / 196.0f);
    }
}

// ---------------- kernel 3: split-K=16 GEMM, double-buffered, 6x8 tile, f32x2 ----------------
#define BM 48
#define BN 128
#define BK 16
#define KSEG (Cc / KSPLIT)   // 128
#define NIT  (KSEG / BK)     // 8

__global__ void __launch_bounds__(128) gemm_kernel(const float* __restrict__ Wm) {
    __shared__ float As[2][BK][BM];
    __shared__ float Bs[2][BK][BN + 4];

    int m0 = blockIdx.y * BM;
    int n0 = blockIdx.x * BN;
    int ks = blockIdx.z;
    int kbase = ks * KSEG;

    int tid = threadIdx.x;          // 128
    int ti = tid & 7;               // 8 m-groups of 6
    int tj = tid >> 3;              // 16 n-groups of 8

    unsigned long long acc2[6][4] = {};

    float  a_r[6];
    float4 b_r[4];

    const float* wrow = Wm + (size_t)(n0 + tid) * Cc + kbase;

    #pragma unroll
    for (int q = 0; q < 6; q++) {
        int e = tid + q * 128;
        a_r[q] = g_pooled[m0 + (e >> 4)][kbase + (e & 15)];
    }
    #pragma unroll
    for (int j = 0; j < 4; j++)
        b_r[j] = reinterpret_cast<const float4*>(wrow)[j];
    #pragma unroll
    for (int q = 0; q < 6; q++) {
        int e = tid + q * 128;
        As[0][e & 15][e >> 4] = a_r[q];
    }
    #pragma unroll
    for (int j = 0; j < 4; j++) {
        Bs[0][4 * j + 0][tid] = b_r[j].x;
        Bs[0][4 * j + 1][tid] = b_r[j].y;
        Bs[0][4 * j + 2][tid] = b_r[j].z;
        Bs[0][4 * j + 3][tid] = b_r[j].w;
    }
    __syncthreads();

    int buf = 0;
    for (int it = 0; it < NIT; it++) {
        if (it + 1 < NIT) {
            int k0 = (it + 1) * BK;
            #pragma unroll
            for (int q = 0; q < 6; q++) {
                int e = tid + q * 128;
                a_r[q] = g_pooled[m0 + (e >> 4)][kbase + k0 + (e & 15)];
            }
            #pragma unroll
            for (int j = 0; j < 4; j++)
                b_r[j] = reinterpret_cast<const float4*>(wrow + k0)[j];
        }

        #pragma unroll
        for (int kk = 0; kk < BK; kk++) {
            unsigned long long bb[4];
            const float* brow = &Bs[buf][kk][tj * 8];
            #pragma unroll
            for (int v = 0; v < 2; v++) {
                float4 bv = *reinterpret_cast<const float4*>(brow + 4 * v);
                asm("mov.b64 %0, {%1, %2};" : "=l"(bb[2*v])   : "f"(bv.x), "f"(bv.y));
                asm("mov.b64 %0, {%1, %2};" : "=l"(bb[2*v+1]) : "f"(bv.z), "f"(bv.w));
            }
            const float* arow = &As[buf][kk][ti * 6];
            #pragma unroll
            for (int u = 0; u < 6; u++) {
                float av = arow[u];
                unsigned long long ad;
                asm("mov.b64 %0, {%1, %1};" : "=l"(ad) : "f"(av));
                #pragma unroll
                for (int v = 0; v < 4; v++)
                    asm("fma.rn.f32x2 %0, %1, %2, %0;" : "+l"(acc2[u][v]) : "l"(ad), "l"(bb[v]));
            }
        }

        if (it + 1 < NIT) {
            int nb = buf ^ 1;
            #pragma unroll
            for (int q = 0; q < 6; q++) {
                int e = tid + q * 128;
                As[nb][e & 15][e >> 4] = a_r[q];
            }
            #pragma unroll
            for (int j = 0; j < 4; j++) {
                Bs[nb][4 * j + 0][tid] = b_r[j].x;
                Bs[nb][4 * j + 1][tid] = b_r[j].y;
                Bs[nb][4 * j + 2][tid] = b_r[j].z;
                Bs[nb][4 * j + 3][tid] = b_r[j].w;
            }
        }
        __syncthreads();
        buf ^= 1;
    }

    #pragma unroll
    for (int u = 0; u < 6; u++) {
        int m = m0 + ti * 6 + u;
        float* prow = &g_part[ks][m][n0 + tj * 8];
        #pragma unroll
        for (int v = 0; v < 4; v++)
            *reinterpret_cast<unsigned long long*>(&prow[2 * v]) = acc2[u][v];
    }
}

// ---------------- kernel 4: combine partials + bias + mask + permute ----------------
__global__ void combine_kernel(const float* __restrict__ bias,
                               float* __restrict__ out) {
    int m = blockIdx.x;                         // 144
    int n = blockIdx.y * 256 + threadIdx.x;     // 2048
    int bimg = m / TOP;
    float v = 0.0f;
    if (g_valid[m]) {
        v = bias[n];
        #pragma unroll
        for (int s = 0; s < KSPLIT; s++)
            v += g_part[s][m][n];
    }
    out[((size_t)(bimg * TOP + g_dest[m])) * Dd + n] = v;
}

// ---------------- launch ----------------
extern "C" void kernel_launch(void* const* d_in, const int* in_sizes, int n_in,
                              void* d_out, int out_size) {
    const float* boxes  = (const float*)d_in[0];
    const float* scores = (const float*)d_in[1];
    const float* f0     = (const float*)d_in[2];
    const float* f1     = (const float*)d_in[3];
    const float* f2     = (const float*)d_in[4];
    const float* f3     = (const float*)d_in[5];
    const float* Wm     = (const float*)d_in[6];
    const float* bias   = (const float*)d_in[7];
    float* out = (float*)d_out;

    cudaFuncSetAttribute(pool_kernel,
                         cudaFuncAttributeMaxDynamicSharedMemorySize,
                         POOL_SMEM_BYTES);

    select_kernel<<<Bsz, 128>>>(boxes, scores);
    pool_kernel<<<dim3(Cc, Bsz), 128, POOL_SMEM_BYTES>>>(f0, f1, f2, f3);
    gemm_kernel<<<dim3(Dd / BN, NROI / BM, KSPLIT), 128>>>(Wm);
    combine_kernel<<<dim3(NROI, Dd / 256), 256>>>(bias, out);
}

// round 11
// speedup vs baseline: 2.1980x; 2.1980x over previous
#include <cuda_runtime.h>
#include <cuda_bf16.h>

#define Bsz 4
#define Nn 300
#define TOP 36
#define Cc 2048
#define Dd 2048
#define NROI (Bsz*TOP)
#define KSPLIT 8
#define KSEG (Cc / KSPLIT)   // 256

// ---------------- scratch (device globals, no allocation) ----------------
__device__ int   g_valid[NROI];
__device__ int   g_level[NROI];
__device__ int   g_dest[NROI];
__device__ int   g_ny[NROI], g_nx[NROI];
__device__ int   g_yi[NROI][28], g_xi[NROI][28];
__device__ float g_yw[NROI][28], g_xw[NROI][28];
__device__ float g_pooled[NROI][Cc];
__device__ int   g_order[NROI];
__device__ float g_part[KSPLIT][NROI][Dd];

// bf16 hi/lo decompositions (tensor-core GEMM inputs)
__device__ __align__(16) __nv_bfloat16 g_Wh[(size_t)Dd * Cc];
__device__ __align__(16) __nv_bfloat16 g_Wl[(size_t)Dd * Cc];
__device__ __align__(16) __nv_bfloat16 g_Ph[NROI][Cc];
__device__ __align__(16) __nv_bfloat16 g_Pl[NROI][Cc];

__device__ __forceinline__ int level_size(int l) {
    return (l == 0) ? 100 : (l == 1) ? 50 : (l == 2) ? 25 : 13;
}

// split a,b into bf16 hi + bf16 residual, packed as bf16x2 words
__device__ __forceinline__ void split2(float a, float b, unsigned& h, unsigned& l) {
    __nv_bfloat16 ha = __float2bfloat16(a);
    __nv_bfloat16 hb = __float2bfloat16(b);
    float ra = a - __bfloat162float(ha);
    float rb = b - __bfloat162float(hb);
    __nv_bfloat162 H; H.x = ha; H.y = hb;
    __nv_bfloat162 L; L.x = __float2bfloat16(ra); L.y = __float2bfloat16(rb);
    h = *reinterpret_cast<unsigned*>(&H);
    l = *reinterpret_cast<unsigned*>(&L);
}

// Streaming separable axis table: 14 monotone samples -> merged (idx, weight)
// list (<=28 entries). Exactly replicates reference bilinear accumulation.
__device__ int build_axis(float start, float rlen, int Hs, int* gidx, float* gwt) {
    int   li[28];
    float lw[28];
    int n = 0;
    float step7  = rlen / 7.0f;
    float step14 = rlen / 14.0f;
    for (int i = 0; i < 14; i++) {
        float yy = start + (float)(i >> 1) * step7 + ((float)(i & 1) + 0.5f) * step14;
        if (yy < -1.0f || yy > (float)Hs) continue;
        float yc = fminf(fmaxf(yy, 0.0f), (float)Hs - 1.0f);
        int i0 = (int)floorf(yc);
        int i1 = min(i0 + 1, Hs - 1);
        float w = yc - (float)i0;
        float w0 = 1.0f - w;
        if (n > 0 && li[n-1] == i0)      lw[n-1] += w0;
        else if (n > 1 && li[n-2] == i0) lw[n-2] += w0;
        else { li[n] = i0; lw[n] = w0; n++; }
        if (n > 0 && li[n-1] == i1)      lw[n-1] += w;
        else if (n > 1 && li[n-2] == i1) lw[n-2] += w;
        else { li[n] = i1; lw[n] = w; n++; }
    }
    for (int t = 0; t < n; t++) { gidx[t] = li[t]; gwt[t] = lw[t]; }
    return n;
}

// ---------------- kernel 0: W -> bf16 hi/lo (no deps, runs first) ----------------
__global__ void wconv_kernel(const float* __restrict__ Wm) {
    int row = blockIdx.x;
    int j   = threadIdx.x;   // 256 threads, 8 cols each
    const float4* src = reinterpret_cast<const float4*>(Wm + (size_t)row * Cc);
    float4 v0 = src[2 * j], v1 = src[2 * j + 1];
    unsigned h0, l0, h1, l1, h2, l2, h3, l3;
    split2(v0.x, v0.y, h0, l0);
    split2(v0.z, v0.w, h1, l1);
    split2(v1.x, v1.y, h2, l2);
    split2(v1.z, v1.w, h3, l3);
    uint4 H = make_uint4(h0, h1, h2, h3);
    uint4 L = make_uint4(l0, l1, l2, l3);
    reinterpret_cast<uint4*>(g_Wh)[row * 256 + j] = H;
    reinterpret_cast<uint4*>(g_Wl)[row * 256 + j] = L;
}

// ---------------- kernel 1: filter + sort + warp NMS + tables + dest ----------------
__global__ void select_kernel(const float* __restrict__ boxes,
                              const float* __restrict__ scores) {
    int b = blockIdx.x;
    int tid = threadIdx.x;
    __shared__ float ss[Nn];
    __shared__ float sx1[Nn], sy1[Nn], sx2[Nn], sy2[Nn];
    __shared__ int   s_selidx[TOP];
    __shared__ int   s_cnt;
    __shared__ int   s_M;
    __shared__ int   keys[TOP];

    const float* sc = scores + b * Nn;
    const float* bx = boxes + (size_t)b * Nn * 4;

    if (tid == 0) s_M = 0;
    for (int i = tid; i < Nn; i += blockDim.x) ss[i] = sc[i];
    __syncthreads();

    {
        int local = 0;
        for (int i = tid; i < Nn; i += blockDim.x) local += (ss[i] > 0.3f);
        #pragma unroll
        for (int o = 16; o; o >>= 1) local += __shfl_down_sync(0xffffffffu, local, o);
        if ((tid & 31) == 0 && local) atomicAdd(&s_M, local);
    }

    for (int i = tid; i < Nn; i += blockDim.x) {
        float si = ss[i];
        if (si > 0.3f) {
            int rank = 0;
            for (int j = 0; j < Nn; j++) {
                float sj = ss[j];
                rank += (sj > 0.3f) && ((sj > si) || (sj == si && j < i));
            }
            sx1[rank] = bx[i * 4 + 0];
            sy1[rank] = bx[i * 4 + 1];
            sx2[rank] = bx[i * 4 + 2];
            sy2[rank] = bx[i * 4 + 3];
        }
    }
    __syncthreads();

    int M = s_M;

    if (tid < 32) {
        int lane = tid;
        unsigned kmask = 0;
        #pragma unroll
        for (int s2 = 0; s2 < 10; s2++)
            if (lane + 32 * s2 < M) kmask |= (1u << s2);
        int cnt = 0;
        for (int i = 0; i < M; i++) {
            unsigned om = __shfl_sync(0xffffffffu, kmask, i & 31);
            if (!((om >> (i >> 5)) & 1u)) continue;
            if (lane == 0) s_selidx[cnt] = i;
            cnt++;
            if (cnt >= TOP) break;
            float x1 = sx1[i], y1 = sy1[i], x2 = sx2[i], y2 = sy2[i];
            float ai = (x2 - x1) * (y2 - y1);
            #pragma unroll
            for (int s2 = 0; s2 < 10; s2++) {
                int j = lane + 32 * s2;
                if (((kmask >> s2) & 1u) && j > i && j < M) {
                    float jx1 = sx1[j], jy1 = sy1[j], jx2 = sx2[j], jy2 = sy2[j];
                    float xx1 = fmaxf(x1, jx1);
                    float yy1 = fmaxf(y1, jy1);
                    float xx2 = fminf(x2, jx2);
                    float yy2 = fminf(y2, jy2);
                    float inter = fmaxf(xx2 - xx1, 0.0f) * fmaxf(yy2 - yy1, 0.0f);
                    float aj = (jx2 - jx1) * (jy2 - jy1);
                    float iou = inter / (ai + aj - inter);
                    if (iou > 0.7f) kmask &= ~(1u << s2);
                }
            }
        }
        if (lane == 0) s_cnt = cnt;
    }
    __syncthreads();

    if (tid < TOP) {
        int r = tid;
        int roi = b * TOP + r;
        int valid = 0, lvl = 0;
        if (r < s_cnt) {
            valid = 1;
            int i = s_selidx[r];
            float bx0 = sx1[i], bx1 = sy1[i], bx2 = sx2[i], bx3 = sy2[i];
            float dx = bx2 - bx0, dy = bx3 - bx1;
            float diag = sqrtf(dx * dx + dy * dy);
            float lf = floorf(4.0f + log2f(diag / 224.0f * 4.0f));
            lf = fminf(fmaxf(lf, 2.0f), 5.0f);
            lvl = (int)lf - 2;
            int Hs = level_size(lvl);
            float rw = fmaxf(bx2 - bx0, 1.0f);
            float rh = fmaxf(bx3 - bx1, 1.0f);
            g_ny[roi] = build_axis(bx1, rh, Hs, g_yi[roi], g_yw[roi]);
            g_nx[roi] = build_axis(bx0, rw, Hs, g_xi[roi], g_xw[roi]);
        } else {
            g_ny[roi] = 0;
            g_nx[roi] = 0;
        }
        g_valid[roi] = valid;
        g_level[roi] = lvl;
        keys[r] = valid ? (lvl * TOP + r) : (4 * TOP + r);
    }
    __syncthreads();
    if (tid < TOP) {
        int k = keys[tid];
        int d = 0;
        for (int q = 0; q < TOP; q++) d += (keys[q] < k);
        g_dest[b * TOP + tid] = d;
    }
}

// ---------------- kernel 1b: LPT ordering (slow level-0 rois first) ----------------
__global__ void schedule_kernel() {
    __shared__ int keys[NROI];
    int t = threadIdx.x;
    if (t < NROI) {
        int lvl = g_level[t];
        int img = t / TOP;
        keys[t] = g_valid[t] ? (lvl * 8 + img) : 1024;
    }
    __syncthreads();
    if (t < NROI) {
        int k = keys[t];
        int rank = 0;
        for (int j = 0; j < NROI; j++)
            rank += (keys[j] < k) || (keys[j] == k && j < t);
        g_order[rank] = t;
    }
}

// ---------------- kernel 2: ROI pooling (best-known R6 tap-gather) ----------------
// grid: (NROI, 32), block: 256 threads. 64 channels per block.
// Each warp: 8 channels as 2 quads; per iter 4 planes x 2 taps = 8 LDGs in flight.
__global__ void pool_kernel(const float* __restrict__ f0, const float* __restrict__ f1,
                            const float* __restrict__ f2, const float* __restrict__ f3) {
    int roi  = g_order[blockIdx.x];
    int cblk = blockIdx.y;
    int tid  = threadIdx.x;

    if (!g_valid[roi]) {
        if (tid < 64) g_pooled[roi][cblk * 64 + tid] = 0.0f;
        return;
    }

    __shared__ int   soff[784];
    __shared__ float swt[784];

    int lvl = g_level[roi];
    int Hs  = level_size(lvl);
    int HW  = Hs * Hs;
    const float* fm = (lvl == 0) ? f0 : (lvl == 1) ? f1 : (lvl == 2) ? f2 : f3;

    int ny = g_ny[roi], nx = g_nx[roi];
    int n = ny * nx;
    for (int k = tid; k < n; k += 256) {
        int a = k / nx;
        int q = k - a * nx;
        soff[k] = g_yi[roi][a] * Hs + g_xi[roi][q];
        swt[k]  = g_yw[roi][a] * g_xw[roi][q];
    }
    __syncthreads();

    int bimg = roi / TOP;
    int warp = tid >> 5, lane = tid & 31;
    #pragma unroll
    for (int q = 0; q < 2; q++) {
        int c = cblk * 64 + (warp << 3) + (q << 2);
        const float* b0 = fm + ((size_t)(bimg * Cc + c)) * (size_t)HW;
        const float* b1 = b0 + HW;
        const float* b2 = b1 + HW;
        const float* b3 = b2 + HW;
        float a0 = 0.f, a1 = 0.f, a2 = 0.f, a3 = 0.f;
        float a4 = 0.f, a5 = 0.f, a6 = 0.f, a7 = 0.f;
        int k = lane;
        for (; k + 32 < n; k += 64) {
            int   o0 = soff[k],  o1 = soff[k + 32];
            float w0 = swt[k],   w1 = swt[k + 32];
            float v0 = b0[o0], v1 = b1[o0], v2 = b2[o0], v3 = b3[o0];
            float v4 = b0[o1], v5 = b1[o1], v6 = b2[o1], v7 = b3[o1];
            a0 += v0 * w0;  a1 += v1 * w0;  a2 += v2 * w0;  a3 += v3 * w0;
            a4 += v4 * w1;  a5 += v5 * w1;  a6 += v6 * w1;  a7 += v7 * w1;
        }
        if (k < n) {
            int o = soff[k]; float w = swt[k];
            a0 += b0[o] * w;  a1 += b1[o] * w;
            a2 += b2[o] * w;  a3 += b3[o] * w;
        }
        float s0 = a0 + a4, s1 = a1 + a5, s2 = a2 + a6, s3 = a3 + a7;
        #pragma unroll
        for (int o = 16; o; o >>= 1) {
            s0 += __shfl_down_sync(0xffffffffu, s0, o);
            s1 += __shfl_down_sync(0xffffffffu, s1, o);
            s2 += __shfl_down_sync(0xffffffffu, s2, o);
            s3 += __shfl_down_sync(0xffffffffu, s3, o);
        }
        if (lane == 0) {
            g_pooled[roi][c]     = s0 * (1.0f / 196.0f);
            g_pooled[roi][c + 1] = s1 * (1.0f / 196.0f);
            g_pooled[roi][c + 2] = s2 * (1.0f / 196.0f);
            g_pooled[roi][c + 3] = s3 * (1.0f / 196.0f);
        }
    }
}

// ---------------- kernel 2b: pooled -> bf16 hi/lo ----------------
__global__ void pconv_kernel() {
    int r = blockIdx.x;
    int t = threadIdx.x;   // 512 threads x 4 cols
    float4 v = reinterpret_cast<const float4*>(g_pooled[r])[t];
    unsigned h0, l0, h1, l1;
    split2(v.x, v.y, h0, l0);
    split2(v.z, v.w, h1, l1);
    reinterpret_cast<uint2*>(g_Ph[r])[t] = make_uint2(h0, h1);
    reinterpret_cast<uint2*>(g_Pl[r])[t] = make_uint2(l0, l1);
}

// ---------------- kernel 3: tensor-core GEMM (bf16 3-product split) ----------------
// out_part[ks] = P[:, kseg] @ W[:, kseg]^T  via mma.sync.m16n8k16
// block: 384 threads (12 warps = 3m x 4n), tile M=48, N=128, K-seg 256.
#define MMA_BF16(c, a, b0v, b1v)                                             \
    asm volatile("mma.sync.aligned.m16n8k16.row.col.f32.bf16.bf16.f32 "      \
                 "{%0,%1,%2,%3}, {%4,%5,%6,%7}, {%8,%9}, {%0,%1,%2,%3};"     \
                 : "+f"(c[0]), "+f"(c[1]), "+f"(c[2]), "+f"(c[3])            \
                 : "r"(a[0]), "r"(a[1]), "r"(a[2]), "r"(a[3]),               \
                   "r"(b0v), "r"(b1v))

__global__ void __launch_bounds__(384) gemm_kernel() {
    __shared__ __align__(16) __nv_bfloat16 Ah[48][16], Al[48][16];
    __shared__ __align__(16) __nv_bfloat16 Bh[128][16], Bl[128][16];

    int tid  = threadIdx.x;
    int wid  = tid >> 5, lane = tid & 31;
    int n0   = blockIdx.x * 128;
    int m0   = blockIdx.y * 48;
    int ks   = blockIdx.z;
    int kbase = ks * KSEG;

    int wm = wid % 3;          // warp m-row (0..2) -> rows wm*16
    int wn = wid / 3;          // warp n-col (0..3) -> cols wn*32
    int g  = lane >> 2;        // 0..7
    int tc = lane & 3;         // 0..3

    float c[4][4] = {};

    for (int it = 0; it < KSEG / 16; it++) {
        int kk = kbase + it * 16;
        // stage B (128n x 16k, hi+lo) and A (48m x 16k, hi+lo)
        if (tid < 256) {
            int nn = tid >> 1, half = tid & 1;
            size_t off = (size_t)(n0 + nn) * Cc + kk + half * 8;
            uint4 h = *reinterpret_cast<const uint4*>(g_Wh + off);
            uint4 l = *reinterpret_cast<const uint4*>(g_Wl + off);
            *reinterpret_cast<uint4*>(&Bh[nn][half * 8]) = h;
            *reinterpret_cast<uint4*>(&Bl[nn][half * 8]) = l;
        } else if (tid < 352) {
            int u = tid - 256, m = u >> 1, half = u & 1;
            uint4 h = *reinterpret_cast<const uint4*>(&g_Ph[m0 + m][kk + half * 8]);
            uint4 l = *reinterpret_cast<const uint4*>(&g_Pl[m0 + m][kk + half * 8]);
            *reinterpret_cast<uint4*>(&Ah[m][half * 8]) = h;
            *reinterpret_cast<uint4*>(&Al[m][half * 8]) = l;
        }
        __syncthreads();

        // A fragments (m16k16, row-major)
        unsigned ah[4], al[4];
        int ar = wm * 16 + g;
        ah[0] = *reinterpret_cast<unsigned*>(&Ah[ar][2 * tc]);
        ah[1] = *reinterpret_cast<unsigned*>(&Ah[ar + 8][2 * tc]);
        ah[2] = *reinterpret_cast<unsigned*>(&Ah[ar][2 * tc + 8]);
        ah[3] = *reinterpret_cast<unsigned*>(&Ah[ar + 8][2 * tc + 8]);
        al[0] = *reinterpret_cast<unsigned*>(&Al[ar][2 * tc]);
        al[1] = *reinterpret_cast<unsigned*>(&Al[ar + 8][2 * tc]);
        al[2] = *reinterpret_cast<unsigned*>(&Al[ar][2 * tc + 8]);
        al[3] = *reinterpret_cast<unsigned*>(&Al[ar + 8][2 * tc + 8]);

        #pragma unroll
        for (int nf = 0; nf < 4; nf++) {
            int br = wn * 32 + nf * 8 + g;
            unsigned bh0 = *reinterpret_cast<unsigned*>(&Bh[br][2 * tc]);
            unsigned bh1 = *reinterpret_cast<unsigned*>(&Bh[br][2 * tc + 8]);
            unsigned bl0 = *reinterpret_cast<unsigned*>(&Bl[br][2 * tc]);
            unsigned bl1 = *reinterpret_cast<unsigned*>(&Bl[br][2 * tc + 8]);
            MMA_BF16(c[nf], ah, bh0, bh1);   // hi*hi
            MMA_BF16(c[nf], ah, bl0, bl1);   // hi*lo
            MMA_BF16(c[nf], al, bh0, bh1);   // lo*hi
        }
        __syncthreads();
    }

    int mA = m0 + wm * 16 + g;
    int mB = mA + 8;
    #pragma unroll
    for (int nf = 0; nf < 4; nf++) {
        int nc = n0 + wn * 32 + nf * 8 + 2 * tc;
        *reinterpret_cast<float2*>(&g_part[ks][mA][nc]) = make_float2(c[nf][0], c[nf][1]);
        *reinterpret_cast<float2*>(&g_part[ks][mB][nc]) = make_float2(c[nf][2], c[nf][3]);
    }
}

// ---------------- kernel 4: combine partials + bias + mask + permute ----------------
__global__ void combine_kernel(const float* __restrict__ bias,
                               float* __restrict__ out) {
    int m = blockIdx.x;                         // 144
    int n = blockIdx.y * 256 + threadIdx.x;     // 2048
    int bimg = m / TOP;
    float v = 0.0f;
    if (g_valid[m]) {
        v = bias[n];
        #pragma unroll
        for (int s = 0; s < KSPLIT; s++)
            v += g_part[s][m][n];
    }
    out[((size_t)(bimg * TOP + g_dest[m])) * Dd + n] = v;
}

// ---------------- launch ----------------
extern "C" void kernel_launch(void* const* d_in, const int* in_sizes, int n_in,
                              void* d_out, int out_size) {
    const float* boxes  = (const float*)d_in[0];
    const float* scores = (const float*)d_in[1];
    const float* f0     = (const float*)d_in[2];
    const float* f1     = (const float*)d_in[3];
    const float* f2     = (const float*)d_in[4];
    const float* f3     = (const float*)d_in[5];
    const float* Wm     = (const float*)d_in[6];
    const float* bias   = (const float*)d_in[7];
    float* out = (float*)d_out;

    wconv_kernel<<<Dd, 256>>>(Wm);                     // no deps: W -> bf16 hi/lo
    select_kernel<<<Bsz, 128>>>(boxes, scores);
    schedule_kernel<<<1, 160>>>();
    pool_kernel<<<dim3(NROI, 32), 256>>>(f0, f1, f2, f3);
    pconv_kernel<<<NROI, 512>>>();
    gemm_kernel<<<dim3(Dd / 128, NROI / 48, KSPLIT), 384>>>();
    combine_kernel<<<dim3(NROI, Dd / 256), 256>>>(bias, out);
}

// round 12
// speedup vs baseline: 2.2499x; 1.0236x over previous
#include <cuda_runtime.h>
#include <cuda_bf16.h>

#define Bsz 4
#define Nn 300
#define TOP 36
#define Cc 2048
#define Dd 2048
#define NROI (Bsz*TOP)
#define KSPLIT 16
#define KSEG (Cc / KSPLIT)   // 128

// ---------------- scratch (device globals, no allocation) ----------------
__device__ int   g_valid[NROI];
__device__ int   g_level[NROI];
__device__ int   g_dest[NROI];
__device__ int   g_ny[NROI], g_nx[NROI];
__device__ int   g_yi[NROI][28], g_xi[NROI][28];
__device__ float g_yw[NROI][28], g_xw[NROI][28];
__device__ int   g_order[NROI];
__device__ float g_part[KSPLIT][NROI][Dd];

// bf16 hi/lo decompositions (tensor-core GEMM inputs)
__device__ __align__(16) __nv_bfloat16 g_Wh[(size_t)Dd * Cc];
__device__ __align__(16) __nv_bfloat16 g_Wl[(size_t)Dd * Cc];
__device__ __align__(16) __nv_bfloat16 g_Ph[NROI][Cc];
__device__ __align__(16) __nv_bfloat16 g_Pl[NROI][Cc];

__device__ __forceinline__ int level_size(int l) {
    return (l == 0) ? 100 : (l == 1) ? 50 : (l == 2) ? 25 : 13;
}

// split a,b into bf16 hi + bf16 residual, packed as bf16x2 words
__device__ __forceinline__ void split2(float a, float b, unsigned& h, unsigned& l) {
    __nv_bfloat16 ha = __float2bfloat16(a);
    __nv_bfloat16 hb = __float2bfloat16(b);
    float ra = a - __bfloat162float(ha);
    float rb = b - __bfloat162float(hb);
    __nv_bfloat162 H; H.x = ha; H.y = hb;
    __nv_bfloat162 L; L.x = __float2bfloat16(ra); L.y = __float2bfloat16(rb);
    h = *reinterpret_cast<unsigned*>(&H);
    l = *reinterpret_cast<unsigned*>(&L);
}

// Streaming separable axis table: 14 monotone samples -> merged (idx, weight)
// list (<=28 entries). Exactly replicates reference bilinear accumulation.
__device__ int build_axis(float start, float rlen, int Hs, int* gidx, float* gwt) {
    int   li[28];
    float lw[28];
    int n = 0;
    float step7  = rlen / 7.0f;
    float step14 = rlen / 14.0f;
    for (int i = 0; i < 14; i++) {
        float yy = start + (float)(i >> 1) * step7 + ((float)(i & 1) + 0.5f) * step14;
        if (yy < -1.0f || yy > (float)Hs) continue;
        float yc = fminf(fmaxf(yy, 0.0f), (float)Hs - 1.0f);
        int i0 = (int)floorf(yc);
        int i1 = min(i0 + 1, Hs - 1);
        float w = yc - (float)i0;
        float w0 = 1.0f - w;
        if (n > 0 && li[n-1] == i0)      lw[n-1] += w0;
        else if (n > 1 && li[n-2] == i0) lw[n-2] += w0;
        else { li[n] = i0; lw[n] = w0; n++; }
        if (n > 0 && li[n-1] == i1)      lw[n-1] += w;
        else if (n > 1 && li[n-2] == i1) lw[n-2] += w;
        else { li[n] = i1; lw[n] = w; n++; }
    }
    for (int t = 0; t < n; t++) { gidx[t] = li[t]; gwt[t] = lw[t]; }
    return n;
}

// ---------------- kernel 0: W -> bf16 hi/lo ----------------
__global__ void wconv_kernel(const float* __restrict__ Wm) {
    int row = blockIdx.x;
    int j   = threadIdx.x;   // 256 threads, 8 cols each
    const float4* src = reinterpret_cast<const float4*>(Wm + (size_t)row * Cc);
    float4 v0 = src[2 * j], v1 = src[2 * j + 1];
    unsigned h0, l0, h1, l1, h2, l2, h3, l3;
    split2(v0.x, v0.y, h0, l0);
    split2(v0.z, v0.w, h1, l1);
    split2(v1.x, v1.y, h2, l2);
    split2(v1.z, v1.w, h3, l3);
    reinterpret_cast<uint4*>(g_Wh)[row * 256 + j] = make_uint4(h0, h1, h2, h3);
    reinterpret_cast<uint4*>(g_Wl)[row * 256 + j] = make_uint4(l0, l1, l2, l3);
}

// ---------------- kernel 1: filter + sort + warp NMS + tables + dest ----------------
__global__ void select_kernel(const float* __restrict__ boxes,
                              const float* __restrict__ scores) {
    int b = blockIdx.x;
    int tid = threadIdx.x;
    __shared__ float ss[Nn];
    __shared__ float sx1[Nn], sy1[Nn], sx2[Nn], sy2[Nn];
    __shared__ int   s_selidx[TOP];
    __shared__ int   s_cnt;
    __shared__ int   s_M;
    __shared__ int   keys[TOP];

    const float* sc = scores + b * Nn;
    const float* bx = boxes + (size_t)b * Nn * 4;

    if (tid == 0) s_M = 0;
    for (int i = tid; i < Nn; i += blockDim.x) ss[i] = sc[i];
    __syncthreads();

    {
        int local = 0;
        for (int i = tid; i < Nn; i += blockDim.x) local += (ss[i] > 0.3f);
        #pragma unroll
        for (int o = 16; o; o >>= 1) local += __shfl_down_sync(0xffffffffu, local, o);
        if ((tid & 31) == 0 && local) atomicAdd(&s_M, local);
    }

    for (int i = tid; i < Nn; i += blockDim.x) {
        float si = ss[i];
        if (si > 0.3f) {
            int rank = 0;
            for (int j = 0; j < Nn; j++) {
                float sj = ss[j];
                rank += (sj > 0.3f) && ((sj > si) || (sj == si && j < i));
            }
            sx1[rank] = bx[i * 4 + 0];
            sy1[rank] = bx[i * 4 + 1];
            sx2[rank] = bx[i * 4 + 2];
            sy2[rank] = bx[i * 4 + 3];
        }
    }
    __syncthreads();

    int M = s_M;

    if (tid < 32) {
        int lane = tid;
        unsigned kmask = 0;
        #pragma unroll
        for (int s2 = 0; s2 < 10; s2++)
            if (lane + 32 * s2 < M) kmask |= (1u << s2);
        int cnt = 0;
        for (int i = 0; i < M; i++) {
            unsigned om = __shfl_sync(0xffffffffu, kmask, i & 31);
            if (!((om >> (i >> 5)) & 1u)) continue;
            if (lane == 0) s_selidx[cnt] = i;
            cnt++;
            if (cnt >= TOP) break;
            float x1 = sx1[i], y1 = sy1[i], x2 = sx2[i], y2 = sy2[i];
            float ai = (x2 - x1) * (y2 - y1);
            #pragma unroll
            for (int s2 = 0; s2 < 10; s2++) {
                int j = lane + 32 * s2;
                if (((kmask >> s2) & 1u) && j > i && j < M) {
                    float jx1 = sx1[j], jy1 = sy1[j], jx2 = sx2[j], jy2 = sy2[j];
                    float xx1 = fmaxf(x1, jx1);
                    float yy1 = fmaxf(y1, jy1);
                    float xx2 = fminf(x2, jx2);
                    float yy2 = fminf(y2, jy2);
                    float inter = fmaxf(xx2 - xx1, 0.0f) * fmaxf(yy2 - yy1, 0.0f);
                    float aj = (jx2 - jx1) * (jy2 - jy1);
                    float iou = inter / (ai + aj - inter);
                    if (iou > 0.7f) kmask &= ~(1u << s2);
                }
            }
        }
        if (lane == 0) s_cnt = cnt;
    }
    __syncthreads();

    if (tid < TOP) {
        int r = tid;
        int roi = b * TOP + r;
        int valid = 0, lvl = 0;
        if (r < s_cnt) {
            valid = 1;
            int i = s_selidx[r];
            float bx0 = sx1[i], bx1 = sy1[i], bx2 = sx2[i], bx3 = sy2[i];
            float dx = bx2 - bx0, dy = bx3 - bx1;
            float diag = sqrtf(dx * dx + dy * dy);
            float lf = floorf(4.0f + log2f(diag / 224.0f * 4.0f));
            lf = fminf(fmaxf(lf, 2.0f), 5.0f);
            lvl = (int)lf - 2;
            int Hs = level_size(lvl);
            float rw = fmaxf(bx2 - bx0, 1.0f);
            float rh = fmaxf(bx3 - bx1, 1.0f);
            g_ny[roi] = build_axis(bx1, rh, Hs, g_yi[roi], g_yw[roi]);
            g_nx[roi] = build_axis(bx0, rw, Hs, g_xi[roi], g_xw[roi]);
        } else {
            g_ny[roi] = 0;
            g_nx[roi] = 0;
        }
        g_valid[roi] = valid;
        g_level[roi] = lvl;
        keys[r] = valid ? (lvl * TOP + r) : (4 * TOP + r);
    }
    __syncthreads();
    if (tid < TOP) {
        int k = keys[tid];
        int d = 0;
        for (int q = 0; q < TOP; q++) d += (keys[q] < k);
        g_dest[b * TOP + tid] = d;
    }
}

// ---------------- kernel 1b: LPT ordering (slow level-0 rois first) ----------------
__global__ void schedule_kernel() {
    __shared__ int keys[NROI];
    int t = threadIdx.x;
    if (t < NROI) {
        int lvl = g_level[t];
        int img = t / TOP;
        keys[t] = g_valid[t] ? (lvl * 8 + img) : 1024;
    }
    __syncthreads();
    if (t < NROI) {
        int k = keys[t];
        int rank = 0;
        for (int j = 0; j < NROI; j++)
            rank += (keys[j] < k) || (keys[j] == k && j < t);
        g_order[rank] = t;
    }
}

// ---------------- kernel 2: ROI pooling (R6 tap-gather + inline bf16 hi/lo epilogue) ----------------
__global__ void pool_kernel(const float* __restrict__ f0, const float* __restrict__ f1,
                            const float* __restrict__ f2, const float* __restrict__ f3) {
    int roi  = g_order[blockIdx.x];
    int cblk = blockIdx.y;
    int tid  = threadIdx.x;

    if (!g_valid[roi]) {
        if (tid < 64) {
            int c = cblk * 64 + tid;
            g_Ph[roi][c] = __float2bfloat16(0.0f);
            g_Pl[roi][c] = __float2bfloat16(0.0f);
        }
        return;
    }

    __shared__ int   soff[784];
    __shared__ float swt[784];

    int lvl = g_level[roi];
    int Hs  = level_size(lvl);
    int HW  = Hs * Hs;
    const float* fm = (lvl == 0) ? f0 : (lvl == 1) ? f1 : (lvl == 2) ? f2 : f3;

    int ny = g_ny[roi], nx = g_nx[roi];
    int n = ny * nx;
    for (int k = tid; k < n; k += 256) {
        int a = k / nx;
        int q = k - a * nx;
        soff[k] = g_yi[roi][a] * Hs + g_xi[roi][q];
        swt[k]  = g_yw[roi][a] * g_xw[roi][q];
    }
    __syncthreads();

    int bimg = roi / TOP;
    int warp = tid >> 5, lane = tid & 31;
    #pragma unroll
    for (int q = 0; q < 2; q++) {
        int c = cblk * 64 + (warp << 3) + (q << 2);
        const float* b0 = fm + ((size_t)(bimg * Cc + c)) * (size_t)HW;
        const float* b1 = b0 + HW;
        const float* b2 = b1 + HW;
        const float* b3 = b2 + HW;
        float a0 = 0.f, a1 = 0.f, a2 = 0.f, a3 = 0.f;
        float a4 = 0.f, a5 = 0.f, a6 = 0.f, a7 = 0.f;
        int k = lane;
        for (; k + 32 < n; k += 64) {
            int   o0 = soff[k],  o1 = soff[k + 32];
            float w0 = swt[k],   w1 = swt[k + 32];
            float v0 = b0[o0], v1 = b1[o0], v2 = b2[o0], v3 = b3[o0];
            float v4 = b0[o1], v5 = b1[o1], v6 = b2[o1], v7 = b3[o1];
            a0 += v0 * w0;  a1 += v1 * w0;  a2 += v2 * w0;  a3 += v3 * w0;
            a4 += v4 * w1;  a5 += v5 * w1;  a6 += v6 * w1;  a7 += v7 * w1;
        }
        if (k < n) {
            int o = soff[k]; float w = swt[k];
            a0 += b0[o] * w;  a1 += b1[o] * w;
            a2 += b2[o] * w;  a3 += b3[o] * w;
        }
        float s0 = a0 + a4, s1 = a1 + a5, s2 = a2 + a6, s3 = a3 + a7;
        #pragma unroll
        for (int o = 16; o; o >>= 1) {
            s0 += __shfl_down_sync(0xffffffffu, s0, o);
            s1 += __shfl_down_sync(0xffffffffu, s1, o);
            s2 += __shfl_down_sync(0xffffffffu, s2, o);
            s3 += __shfl_down_sync(0xffffffffu, s3, o);
        }
        if (lane == 0) {
            s0 *= (1.0f / 196.0f);  s1 *= (1.0f / 196.0f);
            s2 *= (1.0f / 196.0f);  s3 *= (1.0f / 196.0f);
            unsigned h0, l0, h1, l1;
            split2(s0, s1, h0, l0);
            split2(s2, s3, h1, l1);
            *reinterpret_cast<uint2*>(&g_Ph[roi][c]) = make_uint2(h0, h1);
            *reinterpret_cast<uint2*>(&g_Pl[roi][c]) = make_uint2(l0, l1);
        }
    }
}

// ---------------- kernel 3: tensor-core GEMM v2 ----------------
// Block covers full M=144 (3 m-tiles of 48) x 128 n x KSEG=128 k.
// grid (Dd/128=16, KSPLIT=16) = 256 blocks x 384 threads (12 warps = 3m x 4n).
// Fragments via ldmatrix on 48B-padded rows (conflict-free).
#define MMA_BF16(c, a, b0v, b1v)                                             \
    asm volatile("mma.sync.aligned.m16n8k16.row.col.f32.bf16.bf16.f32 "      \
                 "{%0,%1,%2,%3}, {%4,%5,%6,%7}, {%8,%9}, {%0,%1,%2,%3};"     \
                 : "+f"(c[0]), "+f"(c[1]), "+f"(c[2]), "+f"(c[3])            \
                 : "r"(a[0]), "r"(a[1]), "r"(a[2]), "r"(a[3]),               \
                   "r"(b0v), "r"(b1v))

#define LDSM_X4(r, addr)                                                     \
    asm volatile("ldmatrix.sync.aligned.m8n8.x4.shared.b16 {%0,%1,%2,%3}, [%4];" \
                 : "=r"(r[0]), "=r"(r[1]), "=r"(r[2]), "=r"(r[3]) : "r"(addr))

__global__ void __launch_bounds__(384) gemm_kernel() {
    __shared__ __align__(16) __nv_bfloat16 Ah[144][24], Al[144][24];
    __shared__ __align__(16) __nv_bfloat16 Bh[128][24], Bl[128][24];

    int tid  = threadIdx.x;
    int wid  = tid >> 5, lane = tid & 31;
    int n0   = blockIdx.x * 128;
    int ks   = blockIdx.y;
    int kbase = ks * KSEG;

    int wm = wid % 3;          // warp m-row within 48-tile
    int wn = wid / 3;          // warp n-col (0..3) -> cols wn*32
    int g  = lane >> 3;        // ldmatrix lane group 0..3
    int r  = lane & 7;

    float c[3][4][4] = {};

    // per-lane ldmatrix shared addresses (row part varies per use)
    for (int it = 0; it < KSEG / 16; it++) {
        int kk = kbase + it * 16;
        // stage: 544 slots of (hi,lo) uint4
        for (int slot = tid; slot < 544; slot += 384) {
            if (slot < 256) {
                int nn = slot >> 1, half = slot & 1;
                size_t off = (size_t)(n0 + nn) * Cc + kk + half * 8;
                *reinterpret_cast<uint4*>(&Bh[nn][half * 8]) =
                    *reinterpret_cast<const uint4*>(g_Wh + off);
                *reinterpret_cast<uint4*>(&Bl[nn][half * 8]) =
                    *reinterpret_cast<const uint4*>(g_Wl + off);
            } else {
                int u = slot - 256, m = u >> 1, half = u & 1;
                *reinterpret_cast<uint4*>(&Ah[m][half * 8]) =
                    *reinterpret_cast<const uint4*>(&g_Ph[m][kk + half * 8]);
                *reinterpret_cast<uint4*>(&Al[m][half * 8]) =
                    *reinterpret_cast<const uint4*>(&g_Pl[m][kk + half * 8]);
            }
        }
        __syncthreads();

        // A fragments: 3 m-tiles, hi+lo, via ldmatrix x4
        unsigned ah3[3][4], al3[3][4];
        #pragma unroll
        for (int mb = 0; mb < 3; mb++) {
            int arow = mb * 48 + wm * 16 + (g & 1) * 8 + r;
            int koff = (g >> 1) * 8;
            unsigned sa_h = (unsigned)__cvta_generic_to_shared(&Ah[arow][koff]);
            unsigned sa_l = (unsigned)__cvta_generic_to_shared(&Al[arow][koff]);
            LDSM_X4(ah3[mb], sa_h);
            LDSM_X4(al3[mb], sa_l);
        }

        // B fragments: 2 pairs of n8-tiles (nf = 2p, 2p+1), hi+lo
        #pragma unroll
        for (int p = 0; p < 2; p++) {
            int brow = wn * 32 + p * 16 + (g >> 1) * 8 + r;
            int koff = (g & 1) * 8;
            unsigned sb_h = (unsigned)__cvta_generic_to_shared(&Bh[brow][koff]);
            unsigned sb_l = (unsigned)__cvta_generic_to_shared(&Bl[brow][koff]);
            unsigned bh[4], bl[4];
            LDSM_X4(bh, sb_h);   // bh[0],bh[1] = b0,b1 of nf=2p; bh[2],bh[3] = nf=2p+1
            LDSM_X4(bl, sb_l);
            #pragma unroll
            for (int h = 0; h < 2; h++) {
                int nf = 2 * p + h;
                #pragma unroll
                for (int mb = 0; mb < 3; mb++) {
                    MMA_BF16(c[mb][nf], ah3[mb], bh[2*h], bh[2*h+1]);   // hi*hi
                    MMA_BF16(c[mb][nf], ah3[mb], bl[2*h], bl[2*h+1]);   // hi*lo
                    MMA_BF16(c[mb][nf], al3[mb], bh[2*h], bh[2*h+1]);   // lo*hi
                }
            }
        }
        __syncthreads();
    }

    int gq = lane >> 2;        // 0..7 (output row group)
    int tc = lane & 3;
    #pragma unroll
    for (int mb = 0; mb < 3; mb++) {
        int mA = mb * 48 + wm * 16 + gq;
        int mB = mA + 8;
        #pragma unroll
        for (int nf = 0; nf < 4; nf++) {
            int nc = n0 + wn * 32 + nf * 8 + 2 * tc;
            *reinterpret_cast<float2*>(&g_part[ks][mA][nc]) =
                make_float2(c[mb][nf][0], c[mb][nf][1]);
            *reinterpret_cast<float2*>(&g_part[ks][mB][nc]) =
                make_float2(c[mb][nf][2], c[mb][nf][3]);
        }
    }
}

// ---------------- kernel 4: combine partials + bias + mask + permute ----------------
__global__ void combine_kernel(const float* __restrict__ bias,
                               float* __restrict__ out) {
    int m = blockIdx.x;                         // 144
    int n = blockIdx.y * 256 + threadIdx.x;     // 2048
    int bimg = m / TOP;
    float v = 0.0f;
    if (g_valid[m]) {
        v = bias[n];
        #pragma unroll
        for (int s = 0; s < KSPLIT; s++)
            v += g_part[s][m][n];
    }
    out[((size_t)(bimg * TOP + g_dest[m])) * Dd + n] = v;
}

// ---------------- launch ----------------
extern "C" void kernel_launch(void* const* d_in, const int* in_sizes, int n_in,
                              void* d_out, int out_size) {
    const float* boxes  = (const float*)d_in[0];
    const float* scores = (const float*)d_in[1];
    const float* f0     = (const float*)d_in[2];
    const float* f1     = (const float*)d_in[3];
    const float* f2     = (const float*)d_in[4];
    const float* f3     = (const float*)d_in[5];
    const float* Wm     = (const float*)d_in[6];
    const float* bias   = (const float*)d_in[7];
    float* out = (float*)d_out;

    wconv_kernel<<<Dd, 256>>>(Wm);
    select_kernel<<<Bsz, 128>>>(boxes, scores);
    schedule_kernel<<<1, 160>>>();
    pool_kernel<<<dim3(NROI, 32), 256>>>(f0, f1, f2, f3);
    gemm_kernel<<<dim3(Dd / 128, KSPLIT), 384>>>();
    combine_kernel<<<dim3(NROI, Dd / 256), 256>>>(bias, out);
}